// round 2
// baseline (speedup 1.0000x reference)
#include <cuda_runtime.h>
#include <cstdint>

#define NB   32
#define NQ   300
#define NC   11
#define NT   3200
#define NP   (NB*NQ)      // 9600 predictions
#define PF   20           // floats per pred record
#define PPB  16           // preds per block in main kernel
#define THR  800          // threads per block (25 warps); 800*4 = 3200 targets
#define EPSV 1e-6f

// ---- scratch (no allocations allowed) ----
__device__ float g_pred[NP * PF];   // [0..10] -prob, [11..14] cxcywh, [15..18] xyxy, [19] area
__device__ float g_tcx[NT], g_tcy[NT], g_tw[NT], g_th[NT];
__device__ float g_tx0[NT], g_ty0[NT], g_tx1[NT], g_ty1[NT], g_ta[NT];
__device__ int   g_tlab[NT];

// ---------------- precompute: per-prediction features ----------------
__global__ void pred_feat_kernel(const float* __restrict__ logits,
                                 const float* __restrict__ boxes) {
    int n = blockIdx.x * blockDim.x + threadIdx.x;
    if (n >= NP) return;
    const float* l = logits + n * NC;
    float v[NC];
    float m = -1e30f;
#pragma unroll
    for (int c = 0; c < NC; c++) { v[c] = l[c]; m = fmaxf(m, v[c]); }
    float s = 0.f;
#pragma unroll
    for (int c = 0; c < NC; c++) { v[c] = __expf(v[c] - m); s += v[c]; }
    float inv = __fdividef(1.f, s);
    float* o = g_pred + n * PF;
#pragma unroll
    for (int c = 0; c < NC; c++) o[c] = -v[c] * inv;   // store NEGATED prob
    float cx = boxes[n*4+0], cy = boxes[n*4+1], w = boxes[n*4+2], h = boxes[n*4+3];
    float x0 = cx - 0.5f*w, y0 = cy - 0.5f*h, x1 = cx + 0.5f*w, y1 = cy + 0.5f*h;
    o[11] = cx; o[12] = cy; o[13] = w;  o[14] = h;
    o[15] = x0; o[16] = y0; o[17] = x1; o[18] = y1;
    o[19] = (x1 - x0) * (y1 - y0);
}

// ---------------- precompute: per-target features (SoA) ----------------
__global__ void tgt_feat_kernel(const int* __restrict__ labels,
                                const float* __restrict__ boxes) {
    int t = blockIdx.x * blockDim.x + threadIdx.x;
    if (t >= NT) return;
    float cx = boxes[t*4+0], cy = boxes[t*4+1], w = boxes[t*4+2], h = boxes[t*4+3];
    float x0 = cx - 0.5f*w, y0 = cy - 0.5f*h, x1 = cx + 0.5f*w, y1 = cy + 0.5f*h;
    g_tcx[t] = cx; g_tcy[t] = cy; g_tw[t] = w;  g_th[t] = h;
    g_tx0[t] = x0; g_ty0[t] = y0; g_tx1[t] = x1; g_ty1[t] = y1;
    g_ta[t]  = (x1 - x0) * (y1 - y0);
    g_tlab[t] = labels[t];
}

// one output element: C = negprob + 5*L1 - 2*GIoU
__device__ __forceinline__ float cost_elem(
    float negprob,
    float pcx, float pcy, float pw, float ph,
    float px0, float py0, float px1, float py1, float pa,
    float tcx, float tcy, float tw, float th,
    float tx0, float ty0, float tx1, float ty1, float ta)
{
    float l1 = fabsf(pcx - tcx) + fabsf(pcy - tcy) + fabsf(pw - tw) + fabsf(ph - th);
    float ix = fminf(px1, tx1) - fmaxf(px0, tx0);
    float iy = fminf(py1, ty1) - fmaxf(py0, ty0);
    ix = fmaxf(ix, 0.f);
    iy = fmaxf(iy, 0.f);
    float inter = ix * iy;
    float uni   = pa + ta - inter;
    float iou   = __fdividef(inter, uni + EPSV);
    float ex = fmaxf(px1, tx1) - fminf(px0, tx0);
    float ey = fmaxf(py1, ty1) - fminf(py0, ty0);
    float areac = ex * ey;                      // enclosing box, always >= 0
    float term  = __fdividef(areac - uni, areac + EPSV);
    float giou  = iou - term;
    return fmaf(-2.f, giou, fmaf(5.f, l1, negprob));
}

// ---------------- main cost kernel ----------------
__global__ __launch_bounds__(THR, 1) void cost_kernel(float* __restrict__ out) {
    __shared__ float sp[PPB * PF];
    const int tid = threadIdx.x;

    // stage PPB pred records into shared (contiguous AoS block -> coalesced)
    for (int i = tid; i < PPB * PF; i += THR)
        sp[i] = g_pred[(size_t)blockIdx.x * (PPB * PF) + i];

    // 4 consecutive targets per thread, resident in registers
    const float4 tcx = reinterpret_cast<const float4*>(g_tcx)[tid];
    const float4 tcy = reinterpret_cast<const float4*>(g_tcy)[tid];
    const float4 tw  = reinterpret_cast<const float4*>(g_tw )[tid];
    const float4 th  = reinterpret_cast<const float4*>(g_th )[tid];
    const float4 tx0 = reinterpret_cast<const float4*>(g_tx0)[tid];
    const float4 ty0 = reinterpret_cast<const float4*>(g_ty0)[tid];
    const float4 tx1 = reinterpret_cast<const float4*>(g_tx1)[tid];
    const float4 ty1 = reinterpret_cast<const float4*>(g_ty1)[tid];
    const float4 ta  = reinterpret_cast<const float4*>(g_ta )[tid];
    const int4  lab  = reinterpret_cast<const int4 *>(g_tlab)[tid];

    __syncthreads();

    float* obase = out + (size_t)blockIdx.x * PPB * NT + (size_t)tid * 4;

#pragma unroll 2
    for (int p = 0; p < PPB; p++) {
        const float* pp = sp + p * PF;           // broadcast LDS
        const float pcx = pp[11], pcy = pp[12], pw = pp[13], ph = pp[14];
        const float px0 = pp[15], py0 = pp[16], px1 = pp[17], py1 = pp[18];
        const float pa  = pp[19];

        float4 r;
        r.x = cost_elem(pp[lab.x], pcx, pcy, pw, ph, px0, py0, px1, py1, pa,
                        tcx.x, tcy.x, tw.x, th.x, tx0.x, ty0.x, tx1.x, ty1.x, ta.x);
        r.y = cost_elem(pp[lab.y], pcx, pcy, pw, ph, px0, py0, px1, py1, pa,
                        tcx.y, tcy.y, tw.y, th.y, tx0.y, ty0.y, tx1.y, ty1.y, ta.y);
        r.z = cost_elem(pp[lab.z], pcx, pcy, pw, ph, px0, py0, px1, py1, pa,
                        tcx.z, tcy.z, tw.z, th.z, tx0.z, ty0.z, tx1.z, ty1.z, ta.z);
        r.w = cost_elem(pp[lab.w], pcx, pcy, pw, ph, px0, py0, px1, py1, pa,
                        tcx.w, tcy.w, tw.w, th.w, tx0.w, ty0.w, tx1.w, ty1.w, ta.w);

        *reinterpret_cast<float4*>(obase + (size_t)p * NT) = r;   // STG.128
    }
}

extern "C" void kernel_launch(void* const* d_in, const int* in_sizes, int n_in,
                              void* d_out, int out_size) {
    const float* logits  = (const float*)d_in[0];  // [B,Q,C]
    const float* pboxes  = (const float*)d_in[1];  // [B,Q,4]
    const int*   tlabels = (const int*)  d_in[2];  // [T]
    const float* tboxes  = (const float*)d_in[3];  // [T,4]
    float*       out     = (float*)d_out;          // [B,Q,T]

    pred_feat_kernel<<<(NP + 127) / 128, 128>>>(logits, pboxes);
    tgt_feat_kernel<<<(NT + 127) / 128, 128>>>(tlabels, tboxes);
    cost_kernel<<<NP / PPB, THR>>>(out);
}